// round 9
// baseline (speedup 1.0000x reference)
#include <cuda_runtime.h>
#include <cstdint>
#include <float.h>

#define MAXVAL   5843
#define BATCH    4
#define NROWS    (BATCH * MAXVAL)      // 23372
#define TOP_K    200
#define STEP     30
#define NSTEPS   189
#define NTHREADS 256

#define G_BAND   2048                  // band blocks (launched first, wave 1+)
#define RPB      12                    // rows per band block (2048*12 >= 23372)

__inline__ __device__ float warp_max(float v) {
    #pragma unroll
    for (int o = 16; o > 0; o >>= 1)
        v = fmaxf(v, __shfl_xor_sync(0xFFFFFFFFu, v, o));
    return v;
}
__inline__ __device__ float warp_sum(float v) {
    #pragma unroll
    for (int o = 16; o > 0; o >>= 1)
        v += __shfl_xor_sync(0xFFFFFFFFu, v, o);
    return v;
}

__inline__ __device__ int win_start(int q) { return min(q, NSTEPS - 1) * STEP; }

// Branch-free zero fill of orow[lo..hi) with 16B-aligned streaming stores.
__inline__ __device__ void fill_zero(float* __restrict__ orow, int lo, int hi, int t) {
    if (lo >= hi) return;
    const uintptr_t base = (uintptr_t)(orow + lo);
    int head = (int)(((16u - (base & 15u)) & 15u) >> 2);
    if (head > hi - lo) head = hi - lo;

    if (t < head) orow[lo + t] = 0.0f;

    const int lo2  = lo + head;
    const int nvec = (hi - lo2) >> 2;
    float4* __restrict__ p = (float4*)(orow + lo2);
    const float4 z = make_float4(0.0f, 0.0f, 0.0f, 0.0f);
    for (int k = t; k < nvec; k += NTHREADS)
        __stcs(&p[k], z);

    const int tail_lo = lo2 + (nvec << 2);
    if (t < hi - tail_lo) orow[tail_lo + t] = 0.0f;
}

__global__ __launch_bounds__(NTHREADS)
void masked_softmax_kernel(const float* __restrict__ X, float* __restrict__ out) {
    const int t    = threadIdx.x;
    const int warp = t >> 5;
    const int lane = t & 31;

    if (blockIdx.x < G_BAND) {
        // ───────── band block: 12 rows, all window reads issued up-front ─────────
        const int r0 = blockIdx.x * RPB;
        __shared__ float red[8];

        // Issue ALL window loads first (MLP=12) so DRAM reads complete
        // in the opening microseconds of the kernel.
        float v[RPB];
        #pragma unroll
        for (int i = 0; i < RPB; i++) {
            const int r = r0 + i;
            v[i] = -FLT_MAX;
            if (r < NROWS && t < TOP_K) {
                const int s = win_start(r % MAXVAL);
                v[i] = __ldg(X + (size_t)r * MAXVAL + s + t);
            }
        }

        // Reduce + write each row's 200-wide band.
        #pragma unroll 1
        for (int i = 0; i < RPB; i++) {
            const int r = r0 + i;
            if (r >= NROWS) break;

            // block max
            float m = warp_max(v[i]);
            if (lane == 0) red[warp] = m;
            __syncthreads();
            if (warp == 0) {
                float x = (lane < 8) ? red[lane] : -FLT_MAX;
                x = warp_max(x);
                if (lane == 0) red[0] = x;
            }
            __syncthreads();
            m = red[0];
            __syncthreads();

            // block sum of exp
            float e = (t < TOP_K) ? __expf(v[i] - m) : 0.0f;
            float sm = warp_sum(e);
            if (lane == 0) red[warp] = sm;
            __syncthreads();
            if (warp == 0) {
                float x = (lane < 8) ? red[lane] : 0.0f;
                x = warp_sum(x);
                if (lane == 0) red[0] = x;
            }
            __syncthreads();
            const float inv = __frcp_rn(red[0]);
            __syncthreads();

            if (t < TOP_K) {
                const int s = win_start(r % MAXVAL);
                out[(size_t)r * MAXVAL + s + t] = e * inv;
            }
        }
    } else {
        // ───────── fill block: pure zero stream, zero DRAM reads ─────────
        const int row = blockIdx.x - G_BAND;            // 0 .. NROWS-1
        const int s   = win_start(row % MAXVAL);
        float* __restrict__ orow = out + (size_t)row * MAXVAL;

        fill_zero(orow, 0, s, t);
        fill_zero(orow, s + TOP_K, MAXVAL, t);
    }
}

extern "C" void kernel_launch(void* const* d_in, const int* in_sizes, int n_in,
                              void* d_out, int out_size) {
    const float* X = (const float*)d_in[0];
    float* out = (float*)d_out;
    (void)in_sizes; (void)n_in; (void)out_size;
    masked_softmax_kernel<<<G_BAND + NROWS, NTHREADS>>>(X, out);
}

// round 10
// speedup vs baseline: 1.1386x; 1.1386x over previous
#include <cuda_runtime.h>
#include <cstdint>
#include <float.h>

#define MAXVAL   5843
#define BATCH    4
#define NROWS    (BATCH * MAXVAL)   // 23372
#define TOP_K    200
#define STEP     30
#define NSTEPS   189
#define WPT      7                  // window elems per lane: 7*32 >= 200
#define WARPS_PB 8
#define NTHREADS (WARPS_PB * 32)

__inline__ __device__ float warp_max(float v) {
    #pragma unroll
    for (int o = 16; o > 0; o >>= 1)
        v = fmaxf(v, __shfl_xor_sync(0xFFFFFFFFu, v, o));
    return v;
}
__inline__ __device__ float warp_sum(float v) {
    #pragma unroll
    for (int o = 16; o > 0; o >>= 1)
        v += __shfl_xor_sync(0xFFFFFFFFu, v, o);
    return v;
}

// Zero-fill orow[lo..hi) by ONE warp, 16B-aligned float4 streaming stores.
__inline__ __device__ void fill_zero_warp(float* __restrict__ orow, int lo, int hi, int lane) {
    if (lo >= hi) return;
    const uintptr_t base = (uintptr_t)(orow + lo);
    int head = (int)(((16u - (base & 15u)) & 15u) >> 2);
    if (head > hi - lo) head = hi - lo;

    if (lane < head) orow[lo + lane] = 0.0f;

    const int lo2  = lo + head;
    const int nvec = (hi - lo2) >> 2;
    float4* __restrict__ p = (float4*)(orow + lo2);
    const float4 z = make_float4(0.0f, 0.0f, 0.0f, 0.0f);
    for (int k = lane; k < nvec; k += 32)
        __stcs(&p[k], z);

    const int tail_lo = lo2 + (nvec << 2);
    if (lane < hi - tail_lo) orow[tail_lo + lane] = 0.0f;
}

__global__ __launch_bounds__(NTHREADS)
void masked_softmax_kernel(const float* __restrict__ X, float* __restrict__ out) {
    const int lane = threadIdx.x & 31;
    const int row  = blockIdx.x * WARPS_PB + (threadIdx.x >> 5);
    if (row >= NROWS) return;

    const int q = row % MAXVAL;
    const int s = min(q, NSTEPS - 1) * STEP;        // window start (<= 5640)

    const float* __restrict__ xrow = X   + (size_t)row * MAXVAL + s;
    float*       __restrict__ orow = out + (size_t)row * MAXVAL;

    // ---- load 200-wide window: lane + 32k, k < 7 ----
    float v[WPT];
    #pragma unroll
    for (int k = 0; k < WPT; k++) {
        const int idx = lane + (k << 5);
        v[k] = (idx < TOP_K) ? __ldg(xrow + idx) : -FLT_MAX;
    }

    // ---- warp-only max ----
    float m = v[0];
    #pragma unroll
    for (int k = 1; k < WPT; k++) m = fmaxf(m, v[k]);
    m = warp_max(m);

    // ---- warp-only sum of exp ----
    float e[WPT];
    float acc = 0.0f;
    #pragma unroll
    for (int k = 0; k < WPT; k++) {
        const int idx = lane + (k << 5);
        e[k] = (idx < TOP_K) ? __expf(v[k] - m) : 0.0f;
        acc += e[k];
    }
    acc = warp_sum(acc);
    const float inv = __frcp_rn(acc);

    // ---- band write straight from registers (coalesced per step) ----
    #pragma unroll
    for (int k = 0; k < WPT; k++) {
        const int idx = lane + (k << 5);
        if (idx < TOP_K) orow[s + idx] = e[k] * inv;
    }

    // ---- zero regions, streamed by this warp alone ----
    fill_zero_warp(orow, 0, s, lane);
    fill_zero_warp(orow, s + TOP_K, MAXVAL, lane);
}

extern "C" void kernel_launch(void* const* d_in, const int* in_sizes, int n_in,
                              void* d_out, int out_size) {
    const float* X = (const float*)d_in[0];
    float* out = (float*)d_out;
    (void)in_sizes; (void)n_in; (void)out_size;
    const int nblocks = (NROWS + WARPS_PB - 1) / WARPS_PB;   // 2922
    masked_softmax_kernel<<<nblocks, NTHREADS>>>(X, out);
}

// round 11
// speedup vs baseline: 1.2022x; 1.0559x over previous
#include <cuda_runtime.h>
#include <cstdint>
#include <float.h>

#define MAXVAL   5843
#define BATCH    4
#define NROWS    (BATCH * MAXVAL)   // 23372
#define TOP_K    200
#define STEP     30
#define NSTEPS   189
#define NTHREADS 256
#define WPT      7                  // 7*32 >= 200
#define WARPS_PB 8
#define G_BAND   ((NROWS + WARPS_PB - 1) / WARPS_PB)   // 2922 band blocks, launched first

__inline__ __device__ float warp_max(float v) {
    #pragma unroll
    for (int o = 16; o > 0; o >>= 1)
        v = fmaxf(v, __shfl_xor_sync(0xFFFFFFFFu, v, o));
    return v;
}
__inline__ __device__ float warp_sum(float v) {
    #pragma unroll
    for (int o = 16; o > 0; o >>= 1)
        v += __shfl_xor_sync(0xFFFFFFFFu, v, o);
    return v;
}

__inline__ __device__ int win_start(int q) { return min(q, NSTEPS - 1) * STEP; }

// Zero-fill orow[lo..hi) with all NTHREADS threads, 16B-aligned float4 streaming stores.
__inline__ __device__ void fill_zero(float* __restrict__ orow, int lo, int hi, int t) {
    if (lo >= hi) return;
    const uintptr_t base = (uintptr_t)(orow + lo);
    int head = (int)(((16u - (base & 15u)) & 15u) >> 2);
    if (head > hi - lo) head = hi - lo;

    if (t < head) orow[lo + t] = 0.0f;

    const int lo2  = lo + head;
    const int nvec = (hi - lo2) >> 2;
    float4* __restrict__ p = (float4*)(orow + lo2);
    const float4 z = make_float4(0.0f, 0.0f, 0.0f, 0.0f);
    for (int k = t; k < nvec; k += NTHREADS)
        __stcs(&p[k], z);

    const int tail_lo = lo2 + (nvec << 2);
    if (t < hi - tail_lo) orow[tail_lo + t] = 0.0f;
}

__global__ __launch_bounds__(NTHREADS)
void masked_softmax_kernel(const float* __restrict__ X, float* __restrict__ out) {
    const int t = threadIdx.x;

    if (blockIdx.x < G_BAND) {
        // ── band block: 8 independent warp-rows, all DRAM reads happen here,
        //    in the opening waves of the grid. No barriers, no serialization. ──
        const int lane = t & 31;
        const int row  = blockIdx.x * WARPS_PB + (t >> 5);
        if (row >= NROWS) return;

        const int s = win_start(row % MAXVAL);
        const float* __restrict__ xw = X + (size_t)row * MAXVAL + s;

        float v[WPT];
        #pragma unroll
        for (int k = 0; k < WPT; k++) {
            const int idx = lane + (k << 5);
            v[k] = (idx < TOP_K) ? __ldg(xw + idx) : -FLT_MAX;
        }

        float m = v[0];
        #pragma unroll
        for (int k = 1; k < WPT; k++) m = fmaxf(m, v[k]);
        m = warp_max(m);

        float e[WPT];
        float acc = 0.0f;
        #pragma unroll
        for (int k = 0; k < WPT; k++) {
            const int idx = lane + (k << 5);
            e[k] = (idx < TOP_K) ? __expf(v[k] - m) : 0.0f;
            acc += e[k];
        }
        acc = warp_sum(acc);
        const float inv = __frcp_rn(acc);

        float* __restrict__ ob = out + (size_t)row * MAXVAL + s;
        #pragma unroll
        for (int k = 0; k < WPT; k++) {
            const int idx = lane + (k << 5);
            if (idx < TOP_K) ob[idx] = e[k] * inv;
        }
    } else {
        // ── fill block: R5's proven shape — one row, 256 threads, pure stores,
        //    zero DRAM reads. ──
        const int row = blockIdx.x - G_BAND;            // 0 .. NROWS-1
        const int s   = win_start(row % MAXVAL);
        float* __restrict__ orow = out + (size_t)row * MAXVAL;

        fill_zero(orow, 0, s, t);
        fill_zero(orow, s + TOP_K, MAXVAL, t);
    }
}

extern "C" void kernel_launch(void* const* d_in, const int* in_sizes, int n_in,
                              void* d_out, int out_size) {
    const float* X = (const float*)d_in[0];
    float* out = (float*)d_out;
    (void)in_sizes; (void)n_in; (void)out_size;
    masked_softmax_kernel<<<G_BAND + NROWS, NTHREADS>>>(X, out);
}